// round 12
// baseline (speedup 1.0000x reference)
#include <cuda_runtime.h>
#include <math.h>

#define NF   128   // num_filters
#define NG   50    // num_gauss
#define HID  128   // hidden
#define TE   64    // edges per tile
#define RP   68    // hT row pad: 272B stride -> 16B-aligned, bank-spread
#define MAXN 50000
#define MAXE 800000

typedef unsigned long long u64;

// Scratch (no allocation allowed)
__device__ float g_h[MAXN * NF];     // h = x @ lin1^T
__device__ float g_agg[MAXN * NF];   // segment_sum result
__device__ float g_tmp[MAXN * HID];  // ssp(agg @ lin2^T + b)
__device__ float g_w1T[NG * NF];     // w1 transposed [k][f]
__device__ int   g_idx[2 * MAXE];    // normalized int32 edge indices [src | dst]

__device__ __forceinline__ float ssp(float v) {
    return fmaxf(v, 0.0f) + log1pf(expf(-fabsf(v))) - 0.69314718055994531f;
}

// ---- packed fp32x2 helpers (Blackwell FFMA2) --------------------------------
__device__ __forceinline__ u64 splat2(float a) {
    u64 r; asm("mov.b64 %0, {%1, %1};" : "=l"(r) : "f"(a)); return r;
}
__device__ __forceinline__ u64 pack2(float a, float b) {
    u64 r; asm("mov.b64 %0, {%1, %2};" : "=l"(r) : "f"(a), "f"(b)); return r;
}
__device__ __forceinline__ void fma2(u64& d, u64 a, u64 b) {
    asm("fma.rn.f32x2 %0, %1, %2, %0;" : "+l"(d) : "l"(a), "l"(b));
}
__device__ __forceinline__ float2 unpack2(u64 v) {
    float2 f; asm("mov.b64 {%0, %1}, %2;" : "=f"(f.x), "=f"(f.y) : "l"(v)); return f;
}

// Swizzled index (node_gemm only, proven)
__device__ __forceinline__ int widx(int k, int fg) {
    return k * NF + (((fg) ^ (k & 31)) << 2);
}

// ---------------------------------------------------------------------------
// Fused prep: edge_index dtype detect (per-thread, deterministic) + convert,
// plus w1 transpose. One kernel so edge_kernel lands in the profiled slot.
// ---------------------------------------------------------------------------
__global__ void prep_kernel(const void* __restrict__ ei, const float* __restrict__ w1,
                            int E) {
    const int n2e = 2 * E;
    // dtype detection: int64 indices in [0,50000) have all odd 32-bit words zero.
    // Sample odd words 1..63 (all threads same reads -> L1 broadcast, deterministic).
    bool is64 = true;
    const unsigned int* w = (const unsigned int*)ei;
#pragma unroll
    for (int j = 1; j < 64; j += 2)
        if (j < n2e) is64 &= (w[j] == 0u);

    int i = blockIdx.x * blockDim.x + threadIdx.x;
    if (i < n2e)
        g_idx[i] = is64 ? (int)((const long long*)ei)[i] : ((const int*)ei)[i];
    if (i < NF * NG) {
        int f = i / NG, k = i - f * NG;
        g_w1T[k * NF + f] = w1[i];
    }
}

__global__ void zero_kernel(float4* __restrict__ p, int n4) {
    int i = blockIdx.x * blockDim.x + threadIdx.x;
    if (i < n4) p[i] = make_float4(0.f, 0.f, 0.f, 0.f);
}

// ---------------------------------------------------------------------------
// Node GEMM (unchanged from proven R9)
// ---------------------------------------------------------------------------
template <bool SSP, bool HASB>
__global__ void __launch_bounds__(256)
node_gemm(const float* __restrict__ A, const float* __restrict__ W,
          const float* __restrict__ bias, float* __restrict__ out, int N)
{
    extern __shared__ float sm[];
    float* wT = sm;
    float* aN = sm + NF * NF;

    const int tid = threadIdx.x;
    const int rbase = blockIdx.x * TE;

    for (int i = tid; i < NF * NF; i += 256) {
        int f = i >> 7, k = i & (NF - 1);
        wT[widx(k, f >> 2) + (f & 3)] = W[i];
    }
    {
        const float4 z4 = make_float4(0.f, 0.f, 0.f, 0.f);
        for (int i = tid; i < TE * (NF / 4); i += 256) {
            int r = i >> 5;
            int gr = rbase + r;
            ((float4*)aN)[i] = (gr < N)
                ? ((const float4*)A)[(size_t)gr * (NF / 4) + (i & 31)] : z4;
        }
    }
    __syncthreads();

    const int fg = tid & 31, f0 = fg << 2;
    const int r0 = (tid >> 5) << 3;

    u64 acc[8][2];
#pragma unroll
    for (int i = 0; i < 8; i++) { acc[i][0] = 0ULL; acc[i][1] = 0ULL; }

#pragma unroll 8
    for (int k = 0; k < NF; k++) {
        const ulonglong2 wv = *(const ulonglong2*)&wT[widx(k, fg)];
#pragma unroll
        for (int i = 0; i < 8; i++) {
            u64 aa = splat2(aN[(r0 + i) * NF + k]);
            fma2(acc[i][0], aa, wv.x);
            fma2(acc[i][1], aa, wv.y);
        }
    }

    float4 bv = make_float4(0.f, 0.f, 0.f, 0.f);
    if (HASB) bv = *(const float4*)(bias + f0);

#pragma unroll
    for (int i = 0; i < 8; i++) {
        int gr = rbase + r0 + i;
        if (gr < N) {
            float2 p0 = unpack2(acc[i][0]);
            float2 p1 = unpack2(acc[i][1]);
            float4 v;
            v.x = p0.x + bv.x;
            v.y = p0.y + bv.y;
            v.z = p1.x + bv.z;
            v.w = p1.y + bv.w;
            if (SSP) { v.x = ssp(v.x); v.y = ssp(v.y); v.z = ssp(v.z); v.w = ssp(v.w); }
            *(float4*)(out + (size_t)gr * NF + f0) = v;
        }
    }
}

// ---------------------------------------------------------------------------
// Fused edge kernel (composition of proven pieces):
//  - staging: R9 (coalesced float4 eaR, row-major [e][k])
//  - layer 1: e-packed accumulators from eaR scalar broadcasts (register pack2)
//  - hT [f][e] store: R11's (proven)
//  - layer 2: R11's broadcast-packed loop (23 instr/k vs 33)
//  - epilogue: R10-fixed indexing; metadata in registers (no smem arrays)
// smem = 113,152 B -> true 2 blocks/SM.
// ---------------------------------------------------------------------------
#define EDGE_SMEM_BYTES ((NF*NF + TE*NG + NF*RP) * 4)

__global__ void __launch_bounds__(256, 2)
edge_kernel(const float* __restrict__ ea, const float* __restrict__ ew,
            const float* __restrict__ b1,
            const float* __restrict__ w2, const float* __restrict__ b2,
            const float* __restrict__ h, float* __restrict__ agg, int E)
{
    extern __shared__ float sm[];
    float* w2T = sm;                   // NF*NF  [k][f] plain (lane-spread reads)
    float* eaR = w2T + NF * NF;        // TE*NG  row-major [e][k]
    float* hT  = eaR + TE * NG;        // NF x RP  (layer1 out, [f][e])

    const int tid = threadIdx.x;

    // w2 -> smem once per persistent block
    for (int i = tid; i < NF * NF; i += 256) {
        int f = i >> 7, k = i & (NF - 1);
        w2T[k * NF + f] = w2[i];
    }

    const int fg = tid & 31, f0 = fg << 2;
    const int e0 = (tid >> 5) << 3;    // 8 edges per warp-row (4 packed pairs)
    const float4 b1v = *(const float4*)(b1 + f0);
    const float4 b2v = *(const float4*)(b2 + f0);

    const int ntiles = (E + TE - 1) / TE;
    for (int tile = blockIdx.x; tile < ntiles; tile += gridDim.x) {
        const int ebase = tile * TE;
        __syncthreads();   // smem tile reuse barrier

        // --- stage edge_attr row-major (coalesced float4, R9) ---
        if (ebase + TE <= E) {
            const float4* eag = (const float4*)(ea + (size_t)ebase * NG);
            for (int i = tid; i < (TE * NG) / 4; i += 256)
                ((float4*)eaR)[i] = eag[i];
        } else {
            int valid = (E - ebase) * NG;
            for (int i = tid; i < TE * NG; i += 256)
                eaR[i] = (i < valid) ? ea[(size_t)ebase * NG + i] : 0.f;
        }

        // --- per-thread edge metadata into registers ---
        int gsrc[8], gdst[8]; float eww[8];
        if ((ebase + TE <= E) && ((E & 3) == 0)) {
            int4 s0 = *(const int4*)&g_idx[ebase + e0];
            int4 s1 = *(const int4*)&g_idx[ebase + e0 + 4];
            gsrc[0]=s0.x; gsrc[1]=s0.y; gsrc[2]=s0.z; gsrc[3]=s0.w;
            gsrc[4]=s1.x; gsrc[5]=s1.y; gsrc[6]=s1.z; gsrc[7]=s1.w;
            int4 d0 = *(const int4*)&g_idx[E + ebase + e0];
            int4 d1 = *(const int4*)&g_idx[E + ebase + e0 + 4];
            gdst[0]=d0.x; gdst[1]=d0.y; gdst[2]=d0.z; gdst[3]=d0.w;
            gdst[4]=d1.x; gdst[5]=d1.y; gdst[6]=d1.z; gdst[7]=d1.w;
            float4 w0 = *(const float4*)&ew[ebase + e0];
            float4 w1 = *(const float4*)&ew[ebase + e0 + 4];
            eww[0]=w0.x; eww[1]=w0.y; eww[2]=w0.z; eww[3]=w0.w;
            eww[4]=w1.x; eww[5]=w1.y; eww[6]=w1.z; eww[7]=w1.w;
        } else {
#pragma unroll
            for (int i = 0; i < 8; i++) {
                int ge = ebase + e0 + i;
                gsrc[i] = (ge < E) ? g_idx[ge]     : 0;
                gdst[i] = (ge < E) ? g_idx[E + ge] : 0;
                eww[i]  = (ge < E) ? ew[ge]        : 0.f;
            }
        }
        __syncthreads();

        // --- layer 1: acc[pair][filter]; A pairs packed from eaR broadcasts ---
        u64 acc[4][4];
#pragma unroll
        for (int p = 0; p < 4; p++)
#pragma unroll
            for (int j = 0; j < 4; j++) acc[p][j] = 0ULL;

#pragma unroll 2
        for (int k = 0; k < NG; k++) {
            const float4 w4 = __ldg((const float4*)&g_w1T[k * NF + f0]);
            u64 ws0 = splat2(w4.x), ws1 = splat2(w4.y);
            u64 ws2 = splat2(w4.z), ws3 = splat2(w4.w);
            u64 ap0 = pack2(eaR[(e0 + 0) * NG + k], eaR[(e0 + 1) * NG + k]);
            u64 ap1 = pack2(eaR[(e0 + 2) * NG + k], eaR[(e0 + 3) * NG + k]);
            u64 ap2 = pack2(eaR[(e0 + 4) * NG + k], eaR[(e0 + 5) * NG + k]);
            u64 ap3 = pack2(eaR[(e0 + 6) * NG + k], eaR[(e0 + 7) * NG + k]);
            fma2(acc[0][0], ap0, ws0); fma2(acc[0][1], ap0, ws1);
            fma2(acc[0][2], ap0, ws2); fma2(acc[0][3], ap0, ws3);
            fma2(acc[1][0], ap1, ws0); fma2(acc[1][1], ap1, ws1);
            fma2(acc[1][2], ap1, ws2); fma2(acc[1][3], ap1, ws3);
            fma2(acc[2][0], ap2, ws0); fma2(acc[2][1], ap2, ws1);
            fma2(acc[2][2], ap2, ws2); fma2(acc[2][3], ap2, ws3);
            fma2(acc[3][0], ap3, ws0); fma2(acc[3][1], ap3, ws1);
            fma2(acc[3][2], ap3, ws2); fma2(acc[3][3], ap3, ws3);
        }

        // ssp + store transposed hT[f][e] (R11 proven)
#pragma unroll
        for (int j = 0; j < 4; j++) {
            float bj = (j == 0) ? b1v.x : (j == 1) ? b1v.y : (j == 2) ? b1v.z : b1v.w;
            float2 t0 = unpack2(acc[0][j]);
            float2 t1 = unpack2(acc[1][j]);
            float2 t2 = unpack2(acc[2][j]);
            float2 t3 = unpack2(acc[3][j]);
            float4 v0 = make_float4(ssp(t0.x + bj), ssp(t0.y + bj),
                                    ssp(t1.x + bj), ssp(t1.y + bj));
            float4 v1 = make_float4(ssp(t2.x + bj), ssp(t2.y + bj),
                                    ssp(t3.x + bj), ssp(t3.y + bj));
            *(float4*)&hT[(f0 + j) * RP + e0]     = v0;
            *(float4*)&hT[(f0 + j) * RP + e0 + 4] = v1;
        }
        __syncthreads();   // layer 2 reads all hT rows

        // --- prefetch h[src] gathers (L2-resident), hidden behind layer 2 ---
        float4 hs[8];
#pragma unroll
        for (int i = 0; i < 8; i++)
            hs[i] = *(const float4*)(h + (size_t)gsrc[i] * NF + f0);

        // --- layer 2: K=128, broadcast-packed (R11 proven loop) ---
        u64 acc2[4][4];
#pragma unroll
        for (int p = 0; p < 4; p++)
#pragma unroll
            for (int j = 0; j < 4; j++) acc2[p][j] = 0ULL;

#pragma unroll 2
        for (int k = 0; k < NF; k++) {
            const float4 w4 = *(const float4*)&w2T[k * NF + f0];  // lane-spread, conflict-free
            u64 ws0 = splat2(w4.x), ws1 = splat2(w4.y);
            u64 ws2 = splat2(w4.z), ws3 = splat2(w4.w);
            const ulonglong2 a01 = *(const ulonglong2*)&hT[k * RP + e0];      // broadcast
            const ulonglong2 a23 = *(const ulonglong2*)&hT[k * RP + e0 + 4];  // broadcast
            u64 ap0 = a01.x, ap1 = a01.y, ap2 = a23.x, ap3 = a23.y;
            fma2(acc2[0][0], ap0, ws0); fma2(acc2[0][1], ap0, ws1);
            fma2(acc2[0][2], ap0, ws2); fma2(acc2[0][3], ap0, ws3);
            fma2(acc2[1][0], ap1, ws0); fma2(acc2[1][1], ap1, ws1);
            fma2(acc2[1][2], ap1, ws2); fma2(acc2[1][3], ap1, ws3);
            fma2(acc2[2][0], ap2, ws0); fma2(acc2[2][1], ap2, ws1);
            fma2(acc2[2][2], ap2, ws2); fma2(acc2[2][3], ap2, ws3);
            fma2(acc2[3][0], ap3, ws0); fma2(acc2[3][1], ap3, ws1);
            fma2(acc2[3][2], ap3, ws2); fma2(acc2[3][3], ap3, ws3);
        }

        // --- epilogue: W=(l2+b2)*C, msg = h[src]*W, vector atomic scatter ---
#pragma unroll
        for (int p = 0; p < 4; p++) {
            float2 t0 = unpack2(acc2[p][0]);   // .x = edge e0+2p, .y = e0+2p+1
            float2 t1 = unpack2(acc2[p][1]);
            float2 t2 = unpack2(acc2[p][2]);
            float2 t3 = unpack2(acc2[p][3]);
            int la = 2 * p, lb = la + 1;       // local indices 0..7
            if (ebase + e0 + la < E) {
                float ca = 0.5f * (cospif(eww[la] * 0.1f) + 1.0f);
                float4 ma = make_float4((t0.x + b2v.x) * ca * hs[la].x,
                                        (t1.x + b2v.y) * ca * hs[la].y,
                                        (t2.x + b2v.z) * ca * hs[la].z,
                                        (t3.x + b2v.w) * ca * hs[la].w);
                atomicAdd((float4*)(agg + (size_t)gdst[la] * NF + f0), ma);
            }
            if (ebase + e0 + lb < E) {
                float cb = 0.5f * (cospif(eww[lb] * 0.1f) + 1.0f);
                float4 mb = make_float4((t0.y + b2v.x) * cb * hs[lb].x,
                                        (t1.y + b2v.y) * cb * hs[lb].y,
                                        (t2.y + b2v.z) * cb * hs[lb].z,
                                        (t3.y + b2v.w) * cb * hs[lb].w);
                atomicAdd((float4*)(agg + (size_t)gdst[lb] * NF + f0), mb);
            }
        }
    }
}

// ---------------------------------------------------------------------------
// launch — order chosen so edge_kernel is the 4th launch (profiled slot)
// ---------------------------------------------------------------------------
extern "C" void kernel_launch(void* const* d_in, const int* in_sizes, int n_in,
                              void* d_out, int out_size)
{
    const float* x      = (const float*)d_in[0];
    const void*  ei     = d_in[1];
    const float* ew     = (const float*)d_in[2];
    const float* ea     = (const float*)d_in[3];
    const float* mlp_w1 = (const float*)d_in[4];
    const float* mlp_b1 = (const float*)d_in[5];
    const float* mlp_w2 = (const float*)d_in[6];
    const float* mlp_b2 = (const float*)d_in[7];
    const float* lin1_w = (const float*)d_in[8];
    const float* lin2_w = (const float*)d_in[9];
    const float* lin2_b = (const float*)d_in[10];
    const float* lin_w  = (const float*)d_in[11];
    const float* lin_b  = (const float*)d_in[12];

    const int N = in_sizes[0] / HID;
    const int E = in_sizes[1] / 2;

    float *hbuf, *aggbuf, *tmpbuf;
    cudaGetSymbolAddress((void**)&hbuf,   g_h);
    cudaGetSymbolAddress((void**)&aggbuf, g_agg);
    cudaGetSymbolAddress((void**)&tmpbuf, g_tmp);

    const int NODE_SMEM = (NF * NF + TE * NF) * 4;   // 98304 B
    cudaFuncSetAttribute(edge_kernel, cudaFuncAttributeMaxDynamicSharedMemorySize, EDGE_SMEM_BYTES);
    cudaFuncSetAttribute(node_gemm<false, false>, cudaFuncAttributeMaxDynamicSharedMemorySize, NODE_SMEM);
    cudaFuncSetAttribute(node_gemm<true,  true >, cudaFuncAttributeMaxDynamicSharedMemorySize, NODE_SMEM);
    cudaFuncSetAttribute(node_gemm<false, true >, cudaFuncAttributeMaxDynamicSharedMemorySize, NODE_SMEM);

    int dev = 0;
    cudaGetDevice(&dev);
    int sms = 148;
    cudaDeviceGetAttribute(&sms, cudaDevAttrMultiProcessorCount, dev);

    // 1. fused prep: idx convert (+dtype detect) and w1 transpose
    {
        int nthr = 2 * E > NF * NG ? 2 * E : NF * NG;
        prep_kernel<<<(nthr + 255) / 256, 256>>>(ei, mlp_w1, E);
    }
    // 2. zero agg
    {
        int n4 = (N * NF) / 4;
        zero_kernel<<<(n4 + 255) / 256, 256>>>((float4*)aggbuf, n4);
    }
    // 3. h = x @ lin1^T
    node_gemm<false, false><<<(N + TE - 1) / TE, 256, NODE_SMEM>>>(x, lin1_w, nullptr, hbuf, N);
    // 4. fused edge MLP + gather + scatter (persistent, 2 blocks/SM) [profiled]
    edge_kernel<<<2 * sms, 256, EDGE_SMEM_BYTES>>>(ea, ew, mlp_b1,
                                                   mlp_w2, mlp_b2, hbuf, aggbuf, E);
    // 5. tmp = ssp(agg @ lin2^T + b2)
    node_gemm<true, true><<<(N + TE - 1) / TE, 256, NODE_SMEM>>>(aggbuf, lin2_w, lin2_b, tmpbuf, N);
    // 6. out = tmp @ lin^T + b
    node_gemm<false, true><<<(N + TE - 1) / TE, 256, NODE_SMEM>>>(tmpbuf, lin_w, lin_b, (float*)d_out, N);
}

// round 13
// speedup vs baseline: 1.0251x; 1.0251x over previous
#include <cuda_runtime.h>
#include <math.h>

#define NF   128   // num_filters
#define NG   50    // num_gauss
#define HID  128   // hidden
#define TE   64    // edges per tile
#define RP   68    // hT row pad: 272B stride -> 16B-aligned, bank-spread
#define MAXN 50000
#define MAXE 800000

typedef unsigned long long u64;

// Scratch (no allocation allowed)
__device__ float g_h[MAXN * NF];     // h = x @ lin1^T
__device__ float g_agg[MAXN * NF];   // segment_sum result
__device__ float g_tmp[MAXN * HID];  // ssp(agg @ lin2^T + b)
__device__ float g_w1T[NG * NF];     // w1 transposed [k][f]
__device__ int   g_idx[2 * MAXE];    // normalized int32 edge indices [src | dst]

__device__ __forceinline__ float ssp(float v) {
    return fmaxf(v, 0.0f) + log1pf(expf(-fabsf(v))) - 0.69314718055994531f;
}

// ---- packed fp32x2 helpers (Blackwell FFMA2) --------------------------------
__device__ __forceinline__ u64 splat2(float a) {
    u64 r; asm("mov.b64 %0, {%1, %1};" : "=l"(r) : "f"(a)); return r;
}
__device__ __forceinline__ void fma2(u64& d, u64 a, u64 b) {
    asm("fma.rn.f32x2 %0, %1, %2, %0;" : "+l"(d) : "l"(a), "l"(b));
}
__device__ __forceinline__ float2 unpack2(u64 v) {
    float2 f; asm("mov.b64 {%0, %1}, %2;" : "=f"(f.x), "=f"(f.y) : "l"(v)); return f;
}

// Swizzled index (node_gemm only, proven)
__device__ __forceinline__ int widx(int k, int fg) {
    return k * NF + (((fg) ^ (k & 31)) << 2);
}

// ---------------------------------------------------------------------------
// Fused prep (proven R12): idx dtype detect+convert, w1 transpose
// ---------------------------------------------------------------------------
__global__ void prep_kernel(const void* __restrict__ ei, const float* __restrict__ w1,
                            int E) {
    const int n2e = 2 * E;
    bool is64 = true;
    const unsigned int* w = (const unsigned int*)ei;
#pragma unroll
    for (int j = 1; j < 64; j += 2)
        if (j < n2e) is64 &= (w[j] == 0u);

    int i = blockIdx.x * blockDim.x + threadIdx.x;
    if (i < n2e)
        g_idx[i] = is64 ? (int)((const long long*)ei)[i] : ((const int*)ei)[i];
    if (i < NF * NG) {
        int f = i / NG, k = i - f * NG;
        g_w1T[k * NF + f] = w1[i];
    }
}

__global__ void zero_kernel(float4* __restrict__ p, int n4) {
    int i = blockIdx.x * blockDim.x + threadIdx.x;
    if (i < n4) p[i] = make_float4(0.f, 0.f, 0.f, 0.f);
}

// ---------------------------------------------------------------------------
// Node GEMM (unchanged, proven R9)
// ---------------------------------------------------------------------------
template <bool SSP, bool HASB>
__global__ void __launch_bounds__(256)
node_gemm(const float* __restrict__ A, const float* __restrict__ W,
          const float* __restrict__ bias, float* __restrict__ out, int N)
{
    extern __shared__ float sm[];
    float* wT = sm;
    float* aN = sm + NF * NF;

    const int tid = threadIdx.x;
    const int rbase = blockIdx.x * TE;

    for (int i = tid; i < NF * NF; i += 256) {
        int f = i >> 7, k = i & (NF - 1);
        wT[widx(k, f >> 2) + (f & 3)] = W[i];
    }
    {
        const float4 z4 = make_float4(0.f, 0.f, 0.f, 0.f);
        for (int i = tid; i < TE * (NF / 4); i += 256) {
            int r = i >> 5;
            int gr = rbase + r;
            ((float4*)aN)[i] = (gr < N)
                ? ((const float4*)A)[(size_t)gr * (NF / 4) + (i & 31)] : z4;
        }
    }
    __syncthreads();

    const int fg = tid & 31, f0 = fg << 2;
    const int r0 = (tid >> 5) << 3;

    u64 acc[8][2];
#pragma unroll
    for (int i = 0; i < 8; i++) { acc[i][0] = 0ULL; acc[i][1] = 0ULL; }

#pragma unroll 8
    for (int k = 0; k < NF; k++) {
        const ulonglong2 wv = *(const ulonglong2*)&wT[widx(k, fg)];
#pragma unroll
        for (int i = 0; i < 8; i++) {
            u64 aa = splat2(aN[(r0 + i) * NF + k]);
            fma2(acc[i][0], aa, wv.x);
            fma2(acc[i][1], aa, wv.y);
        }
    }

    float4 bv = make_float4(0.f, 0.f, 0.f, 0.f);
    if (HASB) bv = *(const float4*)(bias + f0);

#pragma unroll
    for (int i = 0; i < 8; i++) {
        int gr = rbase + r0 + i;
        if (gr < N) {
            float2 p0 = unpack2(acc[i][0]);
            float2 p1 = unpack2(acc[i][1]);
            float4 v;
            v.x = p0.x + bv.x;
            v.y = p0.y + bv.y;
            v.z = p1.x + bv.z;
            v.w = p1.y + bv.w;
            if (SSP) { v.x = ssp(v.x); v.y = ssp(v.y); v.z = ssp(v.z); v.w = ssp(v.w); }
            *(float4*)(out + (size_t)gr * NF + f0) = v;
        }
    }
}

// ---------------------------------------------------------------------------
// Fused edge kernel R13:
//  - staging: coalesced float4 eaR [e][k]  (proven R9/R12)
//  - in-smem transpose eaR -> eaT [k][e], eaT ALIASED on hT rows 0..49
//    (hT written only after layer 1; extra barrier protects the overlap)
//  - layer 1 AND layer 2 use the same proven 23-instr/k broadcast-packed loop
//  - metadata in smem (sC/sSrc/sDst, R9 pattern) -> registers stay < 128
// smem = 113,920 B -> 2 blocks/SM.
// ---------------------------------------------------------------------------
#define EDGE_SMEM_BYTES ((NF*NF + TE*NG + NF*RP + TE) * 4 + 2 * TE * 4)

__global__ void __launch_bounds__(256, 2)
edge_kernel(const float* __restrict__ ea, const float* __restrict__ ew,
            const float* __restrict__ b1,
            const float* __restrict__ w2, const float* __restrict__ b2,
            const float* __restrict__ h, float* __restrict__ agg, int E)
{
    extern __shared__ float sm[];
    float* w2T  = sm;                    // NF*NF  [k][f] plain
    float* eaR  = w2T + NF * NF;         // TE*NG  row-major [e][k]
    float* hT   = eaR + TE * NG;         // NF x RP ([f][e]); rows 0..49 double as eaT[k][e]
    float* sC   = hT  + NF * RP;         // TE
    int*   sSrc = (int*)(sC + TE);       // TE
    int*   sDst = sSrc + TE;             // TE

    const int tid = threadIdx.x;

    // w2 -> smem once per persistent block
    for (int i = tid; i < NF * NF; i += 256) {
        int f = i >> 7, k = i & (NF - 1);
        w2T[k * NF + f] = w2[i];
    }

    const int fg = tid & 31, f0 = fg << 2;
    const int e0 = (tid >> 5) << 3;      // 8 edges per warp (4 packed pairs)
    const float4 b1v = *(const float4*)(b1 + f0);
    const float4 b2v = *(const float4*)(b2 + f0);

    const int ntiles = (E + TE - 1) / TE;
    for (int tile = blockIdx.x; tile < ntiles; tile += gridDim.x) {
        const int ebase = tile * TE;
        __syncthreads();   // smem tile reuse barrier

        // --- stage edge_attr row-major (coalesced float4) + metadata ---
        if (ebase + TE <= E) {
            const float4* eag = (const float4*)(ea + (size_t)ebase * NG);
            for (int i = tid; i < (TE * NG) / 4; i += 256)
                ((float4*)eaR)[i] = eag[i];
        } else {
            int valid = (E - ebase) * NG;
            for (int i = tid; i < TE * NG; i += 256)
                eaR[i] = (i < valid) ? ea[(size_t)ebase * NG + i] : 0.f;
        }
        if (tid < TE) {
            int ge = ebase + tid;
            if (ge < E) {
                sC[tid]   = 0.5f * (cospif(ew[ge] * 0.1f) + 1.0f);
                sSrc[tid] = g_idx[ge];
                sDst[tid] = g_idx[E + ge];
            } else {
                sC[tid] = 0.f; sSrc[tid] = 0; sDst[tid] = 0;
            }
        }
        __syncthreads();

        // --- transpose eaR[e][k] -> eaT[k][e] (eaT = hT rows 0..49) ---
        for (int i = tid; i < TE * NG; i += 256) {
            int e = i & (TE - 1), k = i >> 6;
            hT[k * RP + e] = eaR[e * NG + k];
        }
        __syncthreads();

        // --- layer 1: same 23-instr/k form as layer 2; w1 via __ldg ---
        u64 acc[4][4];
#pragma unroll
        for (int p = 0; p < 4; p++)
#pragma unroll
            for (int j = 0; j < 4; j++) acc[p][j] = 0ULL;

#pragma unroll 2
        for (int k = 0; k < NG; k++) {
            const float4 w4 = __ldg((const float4*)&g_w1T[k * NF + f0]);
            u64 ws0 = splat2(w4.x), ws1 = splat2(w4.y);
            u64 ws2 = splat2(w4.z), ws3 = splat2(w4.w);
            const ulonglong2 a01 = *(const ulonglong2*)&hT[k * RP + e0];      // broadcast
            const ulonglong2 a23 = *(const ulonglong2*)&hT[k * RP + e0 + 4];  // broadcast
            u64 ap0 = a01.x, ap1 = a01.y, ap2 = a23.x, ap3 = a23.y;
            fma2(acc[0][0], ap0, ws0); fma2(acc[0][1], ap0, ws1);
            fma2(acc[0][2], ap0, ws2); fma2(acc[0][3], ap0, ws3);
            fma2(acc[1][0], ap1, ws0); fma2(acc[1][1], ap1, ws1);
            fma2(acc[1][2], ap1, ws2); fma2(acc[1][3], ap1, ws3);
            fma2(acc[2][0], ap2, ws0); fma2(acc[2][1], ap2, ws1);
            fma2(acc[2][2], ap2, ws2); fma2(acc[2][3], ap2, ws3);
            fma2(acc[3][0], ap3, ws0); fma2(acc[3][1], ap3, ws1);
            fma2(acc[3][2], ap3, ws2); fma2(acc[3][3], ap3, ws3);
        }
        __syncthreads();   // all warps done READING eaT before hT overwrites it

        // --- ssp + store hT[f][e] (proven R11/R12 store) ---
#pragma unroll
        for (int j = 0; j < 4; j++) {
            float bj = (j == 0) ? b1v.x : (j == 1) ? b1v.y : (j == 2) ? b1v.z : b1v.w;
            float2 t0 = unpack2(acc[0][j]);
            float2 t1 = unpack2(acc[1][j]);
            float2 t2 = unpack2(acc[2][j]);
            float2 t3 = unpack2(acc[3][j]);
            float4 v0 = make_float4(ssp(t0.x + bj), ssp(t0.y + bj),
                                    ssp(t1.x + bj), ssp(t1.y + bj));
            float4 v1 = make_float4(ssp(t2.x + bj), ssp(t2.y + bj),
                                    ssp(t3.x + bj), ssp(t3.y + bj));
            *(float4*)&hT[(f0 + j) * RP + e0]     = v0;
            *(float4*)&hT[(f0 + j) * RP + e0 + 4] = v1;
        }
        __syncthreads();   // layer 2 reads all hT rows

        // --- prefetch h[src] gathers (L2-resident), hidden behind layer 2 ---
        float4 hs[8];
#pragma unroll
        for (int i = 0; i < 8; i++)
            hs[i] = *(const float4*)(h + (size_t)sSrc[e0 + i] * NF + f0);

        // --- layer 2: K=128, broadcast-packed (proven loop) ---
        u64 acc2[4][4];
#pragma unroll
        for (int p = 0; p < 4; p++)
#pragma unroll
            for (int j = 0; j < 4; j++) acc2[p][j] = 0ULL;

#pragma unroll 4
        for (int k = 0; k < NF; k++) {
            const float4 w4 = *(const float4*)&w2T[k * NF + f0];  // lane-spread, conflict-free
            u64 ws0 = splat2(w4.x), ws1 = splat2(w4.y);
            u64 ws2 = splat2(w4.z), ws3 = splat2(w4.w);
            const ulonglong2 a01 = *(const ulonglong2*)&hT[k * RP + e0];      // broadcast
            const ulonglong2 a23 = *(const ulonglong2*)&hT[k * RP + e0 + 4];  // broadcast
            u64 ap0 = a01.x, ap1 = a01.y, ap2 = a23.x, ap3 = a23.y;
            fma2(acc2[0][0], ap0, ws0); fma2(acc2[0][1], ap0, ws1);
            fma2(acc2[0][2], ap0, ws2); fma2(acc2[0][3], ap0, ws3);
            fma2(acc2[1][0], ap1, ws0); fma2(acc2[1][1], ap1, ws1);
            fma2(acc2[1][2], ap1, ws2); fma2(acc2[1][3], ap1, ws3);
            fma2(acc2[2][0], ap2, ws0); fma2(acc2[2][1], ap2, ws1);
            fma2(acc2[2][2], ap2, ws2); fma2(acc2[2][3], ap2, ws3);
            fma2(acc2[3][0], ap3, ws0); fma2(acc2[3][1], ap3, ws1);
            fma2(acc2[3][2], ap3, ws2); fma2(acc2[3][3], ap3, ws3);
        }

        // --- epilogue: W=(l2+b2)*C, msg = h[src]*W, vector atomic scatter ---
#pragma unroll
        for (int p = 0; p < 4; p++) {
            float2 t0 = unpack2(acc2[p][0]);   // .x = edge e0+2p, .y = e0+2p+1
            float2 t1 = unpack2(acc2[p][1]);
            float2 t2 = unpack2(acc2[p][2]);
            float2 t3 = unpack2(acc2[p][3]);
            int ia = e0 + 2 * p, ib = ia + 1;  // tile-local smem indices
            int la = 2 * p,      lb = la + 1;  // hs[] local indices
            if (ebase + ia < E) {
                float ca = sC[ia];
                float4 ma = make_float4((t0.x + b2v.x) * ca * hs[la].x,
                                        (t1.x + b2v.y) * ca * hs[la].y,
                                        (t2.x + b2v.z) * ca * hs[la].z,
                                        (t3.x + b2v.w) * ca * hs[la].w);
                atomicAdd((float4*)(agg + (size_t)sDst[ia] * NF + f0), ma);
            }
            if (ebase + ib < E) {
                float cb = sC[ib];
                float4 mb = make_float4((t0.y + b2v.x) * cb * hs[lb].x,
                                        (t1.y + b2v.y) * cb * hs[lb].y,
                                        (t2.y + b2v.z) * cb * hs[lb].z,
                                        (t3.y + b2v.w) * cb * hs[lb].w);
                atomicAdd((float4*)(agg + (size_t)sDst[ib] * NF + f0), mb);
            }
        }
    }
}

// ---------------------------------------------------------------------------
// launch — edge_kernel is the 4th launch (profiled slot)
// ---------------------------------------------------------------------------
extern "C" void kernel_launch(void* const* d_in, const int* in_sizes, int n_in,
                              void* d_out, int out_size)
{
    const float* x      = (const float*)d_in[0];
    const void*  ei     = d_in[1];
    const float* ew     = (const float*)d_in[2];
    const float* ea     = (const float*)d_in[3];
    const float* mlp_w1 = (const float*)d_in[4];
    const float* mlp_b1 = (const float*)d_in[5];
    const float* mlp_w2 = (const float*)d_in[6];
    const float* mlp_b2 = (const float*)d_in[7];
    const float* lin1_w = (const float*)d_in[8];
    const float* lin2_w = (const float*)d_in[9];
    const float* lin2_b = (const float*)d_in[10];
    const float* lin_w  = (const float*)d_in[11];
    const float* lin_b  = (const float*)d_in[12];

    const int N = in_sizes[0] / HID;
    const int E = in_sizes[1] / 2;

    float *hbuf, *aggbuf, *tmpbuf;
    cudaGetSymbolAddress((void**)&hbuf,   g_h);
    cudaGetSymbolAddress((void**)&aggbuf, g_agg);
    cudaGetSymbolAddress((void**)&tmpbuf, g_tmp);

    const int NODE_SMEM = (NF * NF + TE * NF) * 4;   // 98304 B
    cudaFuncSetAttribute(edge_kernel, cudaFuncAttributeMaxDynamicSharedMemorySize, EDGE_SMEM_BYTES);
    cudaFuncSetAttribute(node_gemm<false, false>, cudaFuncAttributeMaxDynamicSharedMemorySize, NODE_SMEM);
    cudaFuncSetAttribute(node_gemm<true,  true >, cudaFuncAttributeMaxDynamicSharedMemorySize, NODE_SMEM);
    cudaFuncSetAttribute(node_gemm<false, true >, cudaFuncAttributeMaxDynamicSharedMemorySize, NODE_SMEM);

    int dev = 0;
    cudaGetDevice(&dev);
    int sms = 148;
    cudaDeviceGetAttribute(&sms, cudaDevAttrMultiProcessorCount, dev);

    // 1. fused prep
    {
        int nthr = 2 * E > NF * NG ? 2 * E : NF * NG;
        prep_kernel<<<(nthr + 255) / 256, 256>>>(ei, mlp_w1, E);
    }
    // 2. zero agg
    {
        int n4 = (N * NF) / 4;
        zero_kernel<<<(n4 + 255) / 256, 256>>>((float4*)aggbuf, n4);
    }
    // 3. h = x @ lin1^T
    node_gemm<false, false><<<(N + TE - 1) / TE, 256, NODE_SMEM>>>(x, lin1_w, nullptr, hbuf, N);
    // 4. fused edge MLP + gather + scatter (persistent, 2 blocks/SM) [profiled]
    edge_kernel<<<2 * sms, 256, EDGE_SMEM_BYTES>>>(ea, ew, mlp_b1,
                                                   mlp_w2, mlp_b2, hbuf, aggbuf, E);
    // 5. tmp = ssp(agg @ lin2^T + b2)
    node_gemm<true, true><<<(N + TE - 1) / TE, 256, NODE_SMEM>>>(aggbuf, lin2_w, lin2_b, tmpbuf, N);
    // 6. out = tmp @ lin^T + b
    node_gemm<false, true><<<(N + TE - 1) / TE, 256, NODE_SMEM>>>(tmpbuf, lin_w, lin_b, (float*)d_out, N);
}

// round 14
// speedup vs baseline: 1.0581x; 1.0321x over previous
#include <cuda_runtime.h>
#include <math.h>

#define NF   128   // num_filters
#define NG   50    // num_gauss
#define HID  128   // hidden
#define TE   64    // edges per tile
#define RP   68    // hT row pad: 272B stride -> 16B-aligned, bank-spread
#define MAXN 50000
#define MAXE 800000

typedef unsigned long long u64;

// Scratch (no allocation allowed)
__device__ float g_h[MAXN * NF];     // h = x @ lin1^T
__device__ float g_agg[MAXN * NF];   // segment_sum result
__device__ float g_tmp[MAXN * HID];  // ssp(agg @ lin2^T + b)
__device__ float g_w1T[NG * NF];     // w1 transposed [k][f]
__device__ int   g_idx[2 * MAXE];    // normalized int32 edge indices [src | dst]

__device__ __forceinline__ float ssp(float v) {
    return fmaxf(v, 0.0f) + log1pf(expf(-fabsf(v))) - 0.69314718055994531f;
}

// ---- packed fp32x2 helpers (Blackwell FFMA2) --------------------------------
__device__ __forceinline__ u64 splat2(float a) {
    u64 r; asm("mov.b64 %0, {%1, %1};" : "=l"(r) : "f"(a)); return r;
}
__device__ __forceinline__ void fma2(u64& d, u64 a, u64 b) {
    asm("fma.rn.f32x2 %0, %1, %2, %0;" : "+l"(d) : "l"(a), "l"(b));
}
__device__ __forceinline__ float2 unpack2(u64 v) {
    float2 f; asm("mov.b64 {%0, %1}, %2;" : "=f"(f.x), "=f"(f.y) : "l"(v)); return f;
}

// Swizzled index (node_gemm only, proven)
__device__ __forceinline__ int widx(int k, int fg) {
    return k * NF + (((fg) ^ (k & 31)) << 2);
}

// ---------------------------------------------------------------------------
// Fused prep (proven R12): idx dtype detect+convert, w1 transpose
// ---------------------------------------------------------------------------
__global__ void prep_kernel(const void* __restrict__ ei, const float* __restrict__ w1,
                            int E) {
    const int n2e = 2 * E;
    bool is64 = true;
    const unsigned int* w = (const unsigned int*)ei;
#pragma unroll
    for (int j = 1; j < 64; j += 2)
        if (j < n2e) is64 &= (w[j] == 0u);

    int i = blockIdx.x * blockDim.x + threadIdx.x;
    if (i < n2e)
        g_idx[i] = is64 ? (int)((const long long*)ei)[i] : ((const int*)ei)[i];
    if (i < NF * NG) {
        int f = i / NG, k = i - f * NG;
        g_w1T[k * NF + f] = w1[i];
    }
}

__global__ void zero_kernel(float4* __restrict__ p, int n4) {
    int i = blockIdx.x * blockDim.x + threadIdx.x;
    if (i < n4) p[i] = make_float4(0.f, 0.f, 0.f, 0.f);
}

// ---------------------------------------------------------------------------
// Node GEMM (unchanged, proven R9)
// ---------------------------------------------------------------------------
template <bool SSP, bool HASB>
__global__ void __launch_bounds__(256)
node_gemm(const float* __restrict__ A, const float* __restrict__ W,
          const float* __restrict__ bias, float* __restrict__ out, int N)
{
    extern __shared__ float sm[];
    float* wT = sm;
    float* aN = sm + NF * NF;

    const int tid = threadIdx.x;
    const int rbase = blockIdx.x * TE;

    for (int i = tid; i < NF * NF; i += 256) {
        int f = i >> 7, k = i & (NF - 1);
        wT[widx(k, f >> 2) + (f & 3)] = W[i];
    }
    {
        const float4 z4 = make_float4(0.f, 0.f, 0.f, 0.f);
        for (int i = tid; i < TE * (NF / 4); i += 256) {
            int r = i >> 5;
            int gr = rbase + r;
            ((float4*)aN)[i] = (gr < N)
                ? ((const float4*)A)[(size_t)gr * (NF / 4) + (i & 31)] : z4;
        }
    }
    __syncthreads();

    const int fg = tid & 31, f0 = fg << 2;
    const int r0 = (tid >> 5) << 3;

    u64 acc[8][2];
#pragma unroll
    for (int i = 0; i < 8; i++) { acc[i][0] = 0ULL; acc[i][1] = 0ULL; }

#pragma unroll 8
    for (int k = 0; k < NF; k++) {
        const ulonglong2 wv = *(const ulonglong2*)&wT[widx(k, fg)];
#pragma unroll
        for (int i = 0; i < 8; i++) {
            u64 aa = splat2(aN[(r0 + i) * NF + k]);
            fma2(acc[i][0], aa, wv.x);
            fma2(acc[i][1], aa, wv.y);
        }
    }

    float4 bv = make_float4(0.f, 0.f, 0.f, 0.f);
    if (HASB) bv = *(const float4*)(bias + f0);

#pragma unroll
    for (int i = 0; i < 8; i++) {
        int gr = rbase + r0 + i;
        if (gr < N) {
            float2 p0 = unpack2(acc[i][0]);
            float2 p1 = unpack2(acc[i][1]);
            float4 v;
            v.x = p0.x + bv.x;
            v.y = p0.y + bv.y;
            v.z = p1.x + bv.z;
            v.w = p1.y + bv.w;
            if (SSP) { v.x = ssp(v.x); v.y = ssp(v.y); v.z = ssp(v.z); v.w = ssp(v.w); }
            *(float4*)(out + (size_t)gr * NF + f0) = v;
        }
    }
}

// ---------------------------------------------------------------------------
// Fused edge kernel R14 = R13 with the gather prefetch removed:
// h[src] is loaded inline in the epilogue (atomics are fire-and-forget, so
// only ~2 gather latencies are exposed per tile) -> 32 registers freed across
// both GEMM loops -> no spills under the 128-reg/2-block cap.
// smem = 113,920 B -> 2 blocks/SM.
// ---------------------------------------------------------------------------
#define EDGE_SMEM_BYTES ((NF*NF + TE*NG + NF*RP + TE) * 4 + 2 * TE * 4)

__global__ void __launch_bounds__(256, 2)
edge_kernel(const float* __restrict__ ea, const float* __restrict__ ew,
            const float* __restrict__ b1,
            const float* __restrict__ w2, const float* __restrict__ b2,
            const float* __restrict__ h, float* __restrict__ agg, int E)
{
    extern __shared__ float sm[];
    float* w2T  = sm;                    // NF*NF  [k][f] plain
    float* eaR  = w2T + NF * NF;         // TE*NG  row-major [e][k]
    float* hT   = eaR + TE * NG;         // NF x RP ([f][e]); rows 0..49 double as eaT[k][e]
    float* sC   = hT  + NF * RP;         // TE
    int*   sSrc = (int*)(sC + TE);       // TE
    int*   sDst = sSrc + TE;             // TE

    const int tid = threadIdx.x;

    // w2 -> smem once per persistent block
    for (int i = tid; i < NF * NF; i += 256) {
        int f = i >> 7, k = i & (NF - 1);
        w2T[k * NF + f] = w2[i];
    }

    const int fg = tid & 31, f0 = fg << 2;
    const int e0 = (tid >> 5) << 3;      // 8 edges per warp (4 packed pairs)
    const float4 b1v = *(const float4*)(b1 + f0);
    const float4 b2v = *(const float4*)(b2 + f0);

    const int ntiles = (E + TE - 1) / TE;
    for (int tile = blockIdx.x; tile < ntiles; tile += gridDim.x) {
        const int ebase = tile * TE;
        __syncthreads();   // smem tile reuse barrier

        // --- stage edge_attr row-major (coalesced float4) + metadata ---
        if (ebase + TE <= E) {
            const float4* eag = (const float4*)(ea + (size_t)ebase * NG);
            for (int i = tid; i < (TE * NG) / 4; i += 256)
                ((float4*)eaR)[i] = eag[i];
        } else {
            int valid = (E - ebase) * NG;
            for (int i = tid; i < TE * NG; i += 256)
                eaR[i] = (i < valid) ? ea[(size_t)ebase * NG + i] : 0.f;
        }
        if (tid < TE) {
            int ge = ebase + tid;
            if (ge < E) {
                sC[tid]   = 0.5f * (cospif(ew[ge] * 0.1f) + 1.0f);
                sSrc[tid] = g_idx[ge];
                sDst[tid] = g_idx[E + ge];
            } else {
                sC[tid] = 0.f; sSrc[tid] = 0; sDst[tid] = 0;
            }
        }
        __syncthreads();

        // --- transpose eaR[e][k] -> eaT[k][e] (eaT = hT rows 0..49) ---
        for (int i = tid; i < TE * NG; i += 256) {
            int e = i & (TE - 1), k = i >> 6;
            hT[k * RP + e] = eaR[e * NG + k];
        }
        __syncthreads();

        // --- layer 1: 23-instr/k broadcast-packed loop; w1 via __ldg ---
        u64 acc[4][4];
#pragma unroll
        for (int p = 0; p < 4; p++)
#pragma unroll
            for (int j = 0; j < 4; j++) acc[p][j] = 0ULL;

#pragma unroll 2
        for (int k = 0; k < NG; k++) {
            const float4 w4 = __ldg((const float4*)&g_w1T[k * NF + f0]);
            u64 ws0 = splat2(w4.x), ws1 = splat2(w4.y);
            u64 ws2 = splat2(w4.z), ws3 = splat2(w4.w);
            const ulonglong2 a01 = *(const ulonglong2*)&hT[k * RP + e0];      // broadcast
            const ulonglong2 a23 = *(const ulonglong2*)&hT[k * RP + e0 + 4];  // broadcast
            u64 ap0 = a01.x, ap1 = a01.y, ap2 = a23.x, ap3 = a23.y;
            fma2(acc[0][0], ap0, ws0); fma2(acc[0][1], ap0, ws1);
            fma2(acc[0][2], ap0, ws2); fma2(acc[0][3], ap0, ws3);
            fma2(acc[1][0], ap1, ws0); fma2(acc[1][1], ap1, ws1);
            fma2(acc[1][2], ap1, ws2); fma2(acc[1][3], ap1, ws3);
            fma2(acc[2][0], ap2, ws0); fma2(acc[2][1], ap2, ws1);
            fma2(acc[2][2], ap2, ws2); fma2(acc[2][3], ap2, ws3);
            fma2(acc[3][0], ap3, ws0); fma2(acc[3][1], ap3, ws1);
            fma2(acc[3][2], ap3, ws2); fma2(acc[3][3], ap3, ws3);
        }
        __syncthreads();   // all warps done READING eaT before hT overwrites it

        // --- ssp + store hT[f][e] ---
#pragma unroll
        for (int j = 0; j < 4; j++) {
            float bj = (j == 0) ? b1v.x : (j == 1) ? b1v.y : (j == 2) ? b1v.z : b1v.w;
            float2 t0 = unpack2(acc[0][j]);
            float2 t1 = unpack2(acc[1][j]);
            float2 t2 = unpack2(acc[2][j]);
            float2 t3 = unpack2(acc[3][j]);
            float4 v0 = make_float4(ssp(t0.x + bj), ssp(t0.y + bj),
                                    ssp(t1.x + bj), ssp(t1.y + bj));
            float4 v1 = make_float4(ssp(t2.x + bj), ssp(t2.y + bj),
                                    ssp(t3.x + bj), ssp(t3.y + bj));
            *(float4*)&hT[(f0 + j) * RP + e0]     = v0;
            *(float4*)&hT[(f0 + j) * RP + e0 + 4] = v1;
        }
        __syncthreads();   // layer 2 reads all hT rows

        // --- layer 2: K=128, broadcast-packed (proven loop) ---
        u64 acc2[4][4];
#pragma unroll
        for (int p = 0; p < 4; p++)
#pragma unroll
            for (int j = 0; j < 4; j++) acc2[p][j] = 0ULL;

#pragma unroll 4
        for (int k = 0; k < NF; k++) {
            const float4 w4 = *(const float4*)&w2T[k * NF + f0];  // lane-spread, conflict-free
            u64 ws0 = splat2(w4.x), ws1 = splat2(w4.y);
            u64 ws2 = splat2(w4.z), ws3 = splat2(w4.w);
            const ulonglong2 a01 = *(const ulonglong2*)&hT[k * RP + e0];      // broadcast
            const ulonglong2 a23 = *(const ulonglong2*)&hT[k * RP + e0 + 4];  // broadcast
            u64 ap0 = a01.x, ap1 = a01.y, ap2 = a23.x, ap3 = a23.y;
            fma2(acc2[0][0], ap0, ws0); fma2(acc2[0][1], ap0, ws1);
            fma2(acc2[0][2], ap0, ws2); fma2(acc2[0][3], ap0, ws3);
            fma2(acc2[1][0], ap1, ws0); fma2(acc2[1][1], ap1, ws1);
            fma2(acc2[1][2], ap1, ws2); fma2(acc2[1][3], ap1, ws3);
            fma2(acc2[2][0], ap2, ws0); fma2(acc2[2][1], ap2, ws1);
            fma2(acc2[2][2], ap2, ws2); fma2(acc2[2][3], ap2, ws3);
            fma2(acc2[3][0], ap3, ws0); fma2(acc2[3][1], ap3, ws1);
            fma2(acc2[3][2], ap3, ws2); fma2(acc2[3][3], ap3, ws3);
        }

        // --- epilogue: gather h[src] INLINE (no long-lived prefetch regs),
        //     W=(l2+b2)*C, msg = h[src]*W, vector atomic scatter ---
#pragma unroll
        for (int p = 0; p < 4; p++) {
            float2 t0 = unpack2(acc2[p][0]);   // .x = edge e0+2p, .y = e0+2p+1
            float2 t1 = unpack2(acc2[p][1]);
            float2 t2 = unpack2(acc2[p][2]);
            float2 t3 = unpack2(acc2[p][3]);
            int ia = e0 + 2 * p, ib = ia + 1;  // tile-local smem indices
            // issue both gathers first (independent), then consume
            float4 hsa = *(const float4*)(h + (size_t)sSrc[ia] * NF + f0);
            float4 hsb = *(const float4*)(h + (size_t)sSrc[ib] * NF + f0);
            if (ebase + ia < E) {
                float ca = sC[ia];
                float4 ma = make_float4((t0.x + b2v.x) * ca * hsa.x,
                                        (t1.x + b2v.y) * ca * hsa.y,
                                        (t2.x + b2v.z) * ca * hsa.z,
                                        (t3.x + b2v.w) * ca * hsa.w);
                atomicAdd((float4*)(agg + (size_t)sDst[ia] * NF + f0), ma);
            }
            if (ebase + ib < E) {
                float cb = sC[ib];
                float4 mb = make_float4((t0.y + b2v.x) * cb * hsb.x,
                                        (t1.y + b2v.y) * cb * hsb.y,
                                        (t2.y + b2v.z) * cb * hsb.z,
                                        (t3.y + b2v.w) * cb * hsb.w);
                atomicAdd((float4*)(agg + (size_t)sDst[ib] * NF + f0), mb);
            }
        }
    }
}

// ---------------------------------------------------------------------------
// launch — edge_kernel is the 4th launch (profiled slot)
// ---------------------------------------------------------------------------
extern "C" void kernel_launch(void* const* d_in, const int* in_sizes, int n_in,
                              void* d_out, int out_size)
{
    const float* x      = (const float*)d_in[0];
    const void*  ei     = d_in[1];
    const float* ew     = (const float*)d_in[2];
    const float* ea     = (const float*)d_in[3];
    const float* mlp_w1 = (const float*)d_in[4];
    const float* mlp_b1 = (const float*)d_in[5];
    const float* mlp_w2 = (const float*)d_in[6];
    const float* mlp_b2 = (const float*)d_in[7];
    const float* lin1_w = (const float*)d_in[8];
    const float* lin2_w = (const float*)d_in[9];
    const float* lin2_b = (const float*)d_in[10];
    const float* lin_w  = (const float*)d_in[11];
    const float* lin_b  = (const float*)d_in[12];

    const int N = in_sizes[0] / HID;
    const int E = in_sizes[1] / 2;

    float *hbuf, *aggbuf, *tmpbuf;
    cudaGetSymbolAddress((void**)&hbuf,   g_h);
    cudaGetSymbolAddress((void**)&aggbuf, g_agg);
    cudaGetSymbolAddress((void**)&tmpbuf, g_tmp);

    const int NODE_SMEM = (NF * NF + TE * NF) * 4;   // 98304 B
    cudaFuncSetAttribute(edge_kernel, cudaFuncAttributeMaxDynamicSharedMemorySize, EDGE_SMEM_BYTES);
    cudaFuncSetAttribute(node_gemm<false, false>, cudaFuncAttributeMaxDynamicSharedMemorySize, NODE_SMEM);
    cudaFuncSetAttribute(node_gemm<true,  true >, cudaFuncAttributeMaxDynamicSharedMemorySize, NODE_SMEM);
    cudaFuncSetAttribute(node_gemm<false, true >, cudaFuncAttributeMaxDynamicSharedMemorySize, NODE_SMEM);

    int dev = 0;
    cudaGetDevice(&dev);
    int sms = 148;
    cudaDeviceGetAttribute(&sms, cudaDevAttrMultiProcessorCount, dev);

    // 1. fused prep
    {
        int nthr = 2 * E > NF * NG ? 2 * E : NF * NG;
        prep_kernel<<<(nthr + 255) / 256, 256>>>(ei, mlp_w1, E);
    }
    // 2. zero agg
    {
        int n4 = (N * NF) / 4;
        zero_kernel<<<(n4 + 255) / 256, 256>>>((float4*)aggbuf, n4);
    }
    // 3. h = x @ lin1^T
    node_gemm<false, false><<<(N + TE - 1) / TE, 256, NODE_SMEM>>>(x, lin1_w, nullptr, hbuf, N);
    // 4. fused edge MLP + gather + scatter (persistent, 2 blocks/SM) [profiled]
    edge_kernel<<<2 * sms, 256, EDGE_SMEM_BYTES>>>(ea, ew, mlp_b1,
                                                   mlp_w2, mlp_b2, hbuf, aggbuf, E);
    // 5. tmp = ssp(agg @ lin2^T + b2)
    node_gemm<true, true><<<(N + TE - 1) / TE, 256, NODE_SMEM>>>(aggbuf, lin2_w, lin2_b, tmpbuf, N);
    // 6. out = tmp @ lin^T + b
    node_gemm<false, true><<<(N + TE - 1) / TE, 256, NODE_SMEM>>>(tmpbuf, lin_w, lin_b, (float*)d_out, N);
}

// round 15
// speedup vs baseline: 1.0848x; 1.0252x over previous
#include <cuda_runtime.h>
#include <math.h>

#define NF   128   // num_filters
#define NG   50    // num_gauss
#define HID  128   // hidden
#define TE   64    // edges per tile
#define RP   68    // hT row pad: 272B stride -> 16B-aligned rows
#define MAXN 50000
#define MAXE 800000

typedef unsigned long long u64;

// Scratch (no allocation allowed)
__device__ float g_h[MAXN * NF];     // h = x @ lin1^T
__device__ float g_agg[MAXN * NF];   // segment_sum result
__device__ float g_tmp[MAXN * HID];  // ssp(agg @ lin2^T + b)
__device__ float g_w1T[NG * NF];     // w1 transposed [k][f]
__device__ int   g_idx[2 * MAXE];    // normalized int32 edge indices [src | dst]

__device__ __forceinline__ float ssp(float v) {
    return fmaxf(v, 0.0f) + log1pf(expf(-fabsf(v))) - 0.69314718055994531f;
}

// ---- packed fp32x2 helpers (Blackwell FFMA2) --------------------------------
__device__ __forceinline__ u64 splat2(float a) {
    u64 r; asm("mov.b64 %0, {%1, %1};" : "=l"(r) : "f"(a)); return r;
}
__device__ __forceinline__ void fma2(u64& d, u64 a, u64 b) {
    asm("fma.rn.f32x2 %0, %1, %2, %0;" : "+l"(d) : "l"(a), "l"(b));
}
__device__ __forceinline__ float2 unpack2(u64 v) {
    float2 f; asm("mov.b64 {%0, %1}, %2;" : "=f"(f.x), "=f"(f.y) : "l"(v)); return f;
}

// Swizzled index (node_gemm only, proven)
__device__ __forceinline__ int widx(int k, int fg) {
    return k * NF + (((fg) ^ (k & 31)) << 2);
}

// ---------------------------------------------------------------------------
// Fused prep (proven R12): idx dtype detect+convert, w1 transpose
// ---------------------------------------------------------------------------
__global__ void prep_kernel(const void* __restrict__ ei, const float* __restrict__ w1,
                            int E) {
    const int n2e = 2 * E;
    bool is64 = true;
    const unsigned int* w = (const unsigned int*)ei;
#pragma unroll
    for (int j = 1; j < 64; j += 2)
        if (j < n2e) is64 &= (w[j] == 0u);

    int i = blockIdx.x * blockDim.x + threadIdx.x;
    if (i < n2e)
        g_idx[i] = is64 ? (int)((const long long*)ei)[i] : ((const int*)ei)[i];
    if (i < NF * NG) {
        int f = i / NG, k = i - f * NG;
        g_w1T[k * NF + f] = w1[i];
    }
}

__global__ void zero_kernel(float4* __restrict__ p, int n4) {
    int i = blockIdx.x * blockDim.x + threadIdx.x;
    if (i < n4) p[i] = make_float4(0.f, 0.f, 0.f, 0.f);
}

// ---------------------------------------------------------------------------
// Node GEMM (unchanged, proven R9)
// ---------------------------------------------------------------------------
template <bool SSP, bool HASB>
__global__ void __launch_bounds__(256)
node_gemm(const float* __restrict__ A, const float* __restrict__ W,
          const float* __restrict__ bias, float* __restrict__ out, int N)
{
    extern __shared__ float sm[];
    float* wT = sm;
    float* aN = sm + NF * NF;

    const int tid = threadIdx.x;
    const int rbase = blockIdx.x * TE;

    for (int i = tid; i < NF * NF; i += 256) {
        int f = i >> 7, k = i & (NF - 1);
        wT[widx(k, f >> 2) + (f & 3)] = W[i];
    }
    {
        const float4 z4 = make_float4(0.f, 0.f, 0.f, 0.f);
        for (int i = tid; i < TE * (NF / 4); i += 256) {
            int r = i >> 5;
            int gr = rbase + r;
            ((float4*)aN)[i] = (gr < N)
                ? ((const float4*)A)[(size_t)gr * (NF / 4) + (i & 31)] : z4;
        }
    }
    __syncthreads();

    const int fg = tid & 31, f0 = fg << 2;
    const int r0 = (tid >> 5) << 3;

    u64 acc[8][2];
#pragma unroll
    for (int i = 0; i < 8; i++) { acc[i][0] = 0ULL; acc[i][1] = 0ULL; }

#pragma unroll 8
    for (int k = 0; k < NF; k++) {
        const ulonglong2 wv = *(const ulonglong2*)&wT[widx(k, fg)];
#pragma unroll
        for (int i = 0; i < 8; i++) {
            u64 aa = splat2(aN[(r0 + i) * NF + k]);
            fma2(acc[i][0], aa, wv.x);
            fma2(acc[i][1], aa, wv.y);
        }
    }

    float4 bv = make_float4(0.f, 0.f, 0.f, 0.f);
    if (HASB) bv = *(const float4*)(bias + f0);

#pragma unroll
    for (int i = 0; i < 8; i++) {
        int gr = rbase + r0 + i;
        if (gr < N) {
            float2 p0 = unpack2(acc[i][0]);
            float2 p1 = unpack2(acc[i][1]);
            float4 v;
            v.x = p0.x + bv.x;
            v.y = p0.y + bv.y;
            v.z = p1.x + bv.z;
            v.w = p1.y + bv.w;
            if (SSP) { v.x = ssp(v.x); v.y = ssp(v.y); v.z = ssp(v.z); v.w = ssp(v.w); }
            *(float4*)(out + (size_t)gr * NF + f0) = v;
        }
    }
}

// ---------------------------------------------------------------------------
// Fused edge kernel R15 = R14 with staging software-pipelined:
//  - next tile's edge_attr prefetched into registers (7x float2/thread,
//    coalesced, row-aligned) DURING current tile's GEMMs -> DRAM latency hidden
//  - STS'd directly transposed into eaT (= hT rows 0..49): eaR buffer and the
//    transpose pass deleted; 4 barriers/tile instead of 5
//  - metadata (ew/src/dst) prefetched the same way
// smem = 101,120 B -> 2 blocks/SM with slack.
// ---------------------------------------------------------------------------
#define EDGE_SMEM_BYTES ((NF*RP + NF*NF + TE) * 4 + 2 * TE * 4)

__global__ void __launch_bounds__(256, 2)
edge_kernel(const float* __restrict__ ea, const float* __restrict__ ew,
            const float* __restrict__ b1,
            const float* __restrict__ w2, const float* __restrict__ b2,
            const float* __restrict__ h, float* __restrict__ agg, int E)
{
    extern __shared__ float sm[];
    float* hT   = sm;                    // NF x RP ([f][e]); rows 0..49 double as eaT[k][e]
    float* w2T  = hT + NF * RP;          // NF*NF  [k][f] plain
    float* sC   = w2T + NF * NF;         // TE
    int*   sSrc = (int*)(sC + TE);       // TE
    int*   sDst = sSrc + TE;             // TE

    const int tid = threadIdx.x;

    // w2 -> smem once per persistent block
    for (int i = tid; i < NF * NF; i += 256) {
        int f = i >> 7, k = i & (NF - 1);
        w2T[k * NF + f] = w2[i];
    }

    const int fg = tid & 31, f0 = fg << 2;
    const int e0 = (tid >> 5) << 3;      // 8 edges per warp (4 packed pairs)
    const float4 b1v = *(const float4*)(b1 + f0);
    const float4 b2v = *(const float4*)(b2 + f0);

    const int ntiles = (E + TE - 1) / TE;

    // --- prologue: prefetch FIRST tile into registers ---
    float2 pf[7];
    float  pmw = 0.f; int psrc = 0, pdst = 0;
    {
        int nb = blockIdx.x * TE;
#pragma unroll
        for (int j = 0; j < 7; j++) {
            int f2 = tid + j * 256;               // float2 slot in [0,1600)
            pf[j] = make_float2(0.f, 0.f);
            if (f2 < (TE * NG) / 2) {
                int e = f2 / (NG / 2), kk = (f2 % (NG / 2)) * 2;
                int ge = nb + e;
                if (ge < E) pf[j] = *(const float2*)&ea[(size_t)ge * NG + kk];
            }
        }
        if (tid < TE) {
            int ge = nb + tid;
            if (ge < E) { pmw = ew[ge]; psrc = g_idx[ge]; pdst = g_idx[E + ge]; }
        }
    }

    for (int tile = blockIdx.x; tile < ntiles; tile += gridDim.x) {
        const int ebase = tile * TE;
        __syncthreads();   // A: hT + metadata free (prev tile fully consumed)

        // --- STS prefetched edge_attr transposed into eaT (= hT rows 0..49) ---
#pragma unroll
        for (int j = 0; j < 7; j++) {
            int f2 = tid + j * 256;
            if (f2 < (TE * NG) / 2) {
                int e = f2 / (NG / 2), kk = (f2 % (NG / 2)) * 2;
                hT[kk * RP + e]       = pf[j].x;
                hT[(kk + 1) * RP + e] = pf[j].y;
            }
        }
        if (tid < TE) {
            sC[tid]   = 0.5f * (cospif(pmw * 0.1f) + 1.0f);
            sSrc[tid] = psrc;
            sDst[tid] = pdst;
        }

        // --- prefetch NEXT tile (consumed next iteration -> latency hidden) ---
        {
            int nb = (tile + gridDim.x) * TE;
#pragma unroll
            for (int j = 0; j < 7; j++) {
                int f2 = tid + j * 256;
                pf[j] = make_float2(0.f, 0.f);
                if (f2 < (TE * NG) / 2) {
                    int e = f2 / (NG / 2), kk = (f2 % (NG / 2)) * 2;
                    int ge = nb + e;
                    if (ge < E) pf[j] = *(const float2*)&ea[(size_t)ge * NG + kk];
                }
            }
            pmw = 0.f; psrc = 0; pdst = 0;
            if (tid < TE) {
                int ge = nb + tid;
                if (ge < E) { pmw = ew[ge]; psrc = g_idx[ge]; pdst = g_idx[E + ge]; }
            }
        }
        __syncthreads();   // B: eaT + metadata (+ w2T on first iter) visible

        // --- layer 1: 23-instr/k broadcast-packed loop; w1 via __ldg ---
        u64 acc[4][4];
#pragma unroll
        for (int p = 0; p < 4; p++)
#pragma unroll
            for (int j = 0; j < 4; j++) acc[p][j] = 0ULL;

#pragma unroll 2
        for (int k = 0; k < NG; k++) {
            const float4 w4 = __ldg((const float4*)&g_w1T[k * NF + f0]);
            u64 ws0 = splat2(w4.x), ws1 = splat2(w4.y);
            u64 ws2 = splat2(w4.z), ws3 = splat2(w4.w);
            const ulonglong2 a01 = *(const ulonglong2*)&hT[k * RP + e0];      // broadcast
            const ulonglong2 a23 = *(const ulonglong2*)&hT[k * RP + e0 + 4];  // broadcast
            u64 ap0 = a01.x, ap1 = a01.y, ap2 = a23.x, ap3 = a23.y;
            fma2(acc[0][0], ap0, ws0); fma2(acc[0][1], ap0, ws1);
            fma2(acc[0][2], ap0, ws2); fma2(acc[0][3], ap0, ws3);
            fma2(acc[1][0], ap1, ws0); fma2(acc[1][1], ap1, ws1);
            fma2(acc[1][2], ap1, ws2); fma2(acc[1][3], ap1, ws3);
            fma2(acc[2][0], ap2, ws0); fma2(acc[2][1], ap2, ws1);
            fma2(acc[2][2], ap2, ws2); fma2(acc[2][3], ap2, ws3);
            fma2(acc[3][0], ap3, ws0); fma2(acc[3][1], ap3, ws1);
            fma2(acc[3][2], ap3, ws2); fma2(acc[3][3], ap3, ws3);
        }
        __syncthreads();   // C: all warps done READING eaT before hT store clobbers

        // --- ssp + store hT[f][e] ---
#pragma unroll
        for (int j = 0; j < 4; j++) {
            float bj = (j == 0) ? b1v.x : (j == 1) ? b1v.y : (j == 2) ? b1v.z : b1v.w;
            float2 t0 = unpack2(acc[0][j]);
            float2 t1 = unpack2(acc[1][j]);
            float2 t2 = unpack2(acc[2][j]);
            float2 t3 = unpack2(acc[3][j]);
            float4 v0 = make_float4(ssp(t0.x + bj), ssp(t0.y + bj),
                                    ssp(t1.x + bj), ssp(t1.y + bj));
            float4 v1 = make_float4(ssp(t2.x + bj), ssp(t2.y + bj),
                                    ssp(t3.x + bj), ssp(t3.y + bj));
            *(float4*)&hT[(f0 + j) * RP + e0]     = v0;
            *(float4*)&hT[(f0 + j) * RP + e0 + 4] = v1;
        }
        __syncthreads();   // D: hT complete before layer 2 reads

        // --- layer 2: K=128, broadcast-packed (proven loop) ---
        u64 acc2[4][4];
#pragma unroll
        for (int p = 0; p < 4; p++)
#pragma unroll
            for (int j = 0; j < 4; j++) acc2[p][j] = 0ULL;

#pragma unroll 4
        for (int k = 0; k < NF; k++) {
            const float4 w4 = *(const float4*)&w2T[k * NF + f0];  // lane-spread, conflict-free
            u64 ws0 = splat2(w4.x), ws1 = splat2(w4.y);
            u64 ws2 = splat2(w4.z), ws3 = splat2(w4.w);
            const ulonglong2 a01 = *(const ulonglong2*)&hT[k * RP + e0];      // broadcast
            const ulonglong2 a23 = *(const ulonglong2*)&hT[k * RP + e0 + 4];  // broadcast
            u64 ap0 = a01.x, ap1 = a01.y, ap2 = a23.x, ap3 = a23.y;
            fma2(acc2[0][0], ap0, ws0); fma2(acc2[0][1], ap0, ws1);
            fma2(acc2[0][2], ap0, ws2); fma2(acc2[0][3], ap0, ws3);
            fma2(acc2[1][0], ap1, ws0); fma2(acc2[1][1], ap1, ws1);
            fma2(acc2[1][2], ap1, ws2); fma2(acc2[1][3], ap1, ws3);
            fma2(acc2[2][0], ap2, ws0); fma2(acc2[2][1], ap2, ws1);
            fma2(acc2[2][2], ap2, ws2); fma2(acc2[2][3], ap2, ws3);
            fma2(acc2[3][0], ap3, ws0); fma2(acc2[3][1], ap3, ws1);
            fma2(acc2[3][2], ap3, ws2); fma2(acc2[3][3], ap3, ws3);
        }

        // --- epilogue: inline gather h[src], W=(l2+b2)*C, vector atomic scatter ---
#pragma unroll
        for (int p = 0; p < 4; p++) {
            float2 t0 = unpack2(acc2[p][0]);   // .x = edge e0+2p, .y = e0+2p+1
            float2 t1 = unpack2(acc2[p][1]);
            float2 t2 = unpack2(acc2[p][2]);
            float2 t3 = unpack2(acc2[p][3]);
            int ia = e0 + 2 * p, ib = ia + 1;  // tile-local smem indices
            float4 hsa = *(const float4*)(h + (size_t)sSrc[ia] * NF + f0);
            float4 hsb = *(const float4*)(h + (size_t)sSrc[ib] * NF + f0);
            if (ebase + ia < E) {
                float ca = sC[ia];
                float4 ma = make_float4((t0.x + b2v.x) * ca * hsa.x,
                                        (t1.x + b2v.y) * ca * hsa.y,
                                        (t2.x + b2v.z) * ca * hsa.z,
                                        (t3.x + b2v.w) * ca * hsa.w);
                atomicAdd((float4*)(agg + (size_t)sDst[ia] * NF + f0), ma);
            }
            if (ebase + ib < E) {
                float cb = sC[ib];
                float4 mb = make_float4((t0.y + b2v.x) * cb * hsb.x,
                                        (t1.y + b2v.y) * cb * hsb.y,
                                        (t2.y + b2v.z) * cb * hsb.z,
                                        (t3.y + b2v.w) * cb * hsb.w);
                atomicAdd((float4*)(agg + (size_t)sDst[ib] * NF + f0), mb);
            }
        }
    }
}

// ---------------------------------------------------------------------------
// launch — edge_kernel is the 4th launch (profiled slot)
// ---------------------------------------------------------------------------
extern "C" void kernel_launch(void* const* d_in, const int* in_sizes, int n_in,
                              void* d_out, int out_size)
{
    const float* x      = (const float*)d_in[0];
    const void*  ei     = d_in[1];
    const float* ew     = (const float*)d_in[2];
    const float* ea     = (const float*)d_in[3];
    const float* mlp_w1 = (const float*)d_in[4];
    const float* mlp_b1 = (const float*)d_in[5];
    const float* mlp_w2 = (const float*)d_in[6];
    const float* mlp_b2 = (const float*)d_in[7];
    const float* lin1_w = (const float*)d_in[8];
    const float* lin2_w = (const float*)d_in[9];
    const float* lin2_b = (const float*)d_in[10];
    const float* lin_w  = (const float*)d_in[11];
    const float* lin_b  = (const float*)d_in[12];

    const int N = in_sizes[0] / HID;
    const int E = in_sizes[1] / 2;

    float *hbuf, *aggbuf, *tmpbuf;
    cudaGetSymbolAddress((void**)&hbuf,   g_h);
    cudaGetSymbolAddress((void**)&aggbuf, g_agg);
    cudaGetSymbolAddress((void**)&tmpbuf, g_tmp);

    const int NODE_SMEM = (NF * NF + TE * NF) * 4;   // 98304 B
    cudaFuncSetAttribute(edge_kernel, cudaFuncAttributeMaxDynamicSharedMemorySize, EDGE_SMEM_BYTES);
    cudaFuncSetAttribute(node_gemm<false, false>, cudaFuncAttributeMaxDynamicSharedMemorySize, NODE_SMEM);
    cudaFuncSetAttribute(node_gemm<true,  true >, cudaFuncAttributeMaxDynamicSharedMemorySize, NODE_SMEM);
    cudaFuncSetAttribute(node_gemm<false, true >, cudaFuncAttributeMaxDynamicSharedMemorySize, NODE_SMEM);

    int dev = 0;
    cudaGetDevice(&dev);
    int sms = 148;
    cudaDeviceGetAttribute(&sms, cudaDevAttrMultiProcessorCount, dev);

    // 1. fused prep
    {
        int nthr = 2 * E > NF * NG ? 2 * E : NF * NG;
        prep_kernel<<<(nthr + 255) / 256, 256>>>(ei, mlp_w1, E);
    }
    // 2. zero agg
    {
        int n4 = (N * NF) / 4;
        zero_kernel<<<(n4 + 255) / 256, 256>>>((float4*)aggbuf, n4);
    }
    // 3. h = x @ lin1^T
    node_gemm<false, false><<<(N + TE - 1) / TE, 256, NODE_SMEM>>>(x, lin1_w, nullptr, hbuf, N);
    // 4. fused edge MLP + gather + scatter (persistent, 2 blocks/SM) [profiled]
    edge_kernel<<<2 * sms, 256, EDGE_SMEM_BYTES>>>(ea, ew, mlp_b1,
                                                   mlp_w2, mlp_b2, hbuf, aggbuf, E);
    // 5. tmp = ssp(agg @ lin2^T + b2)
    node_gemm<true, true><<<(N + TE - 1) / TE, 256, NODE_SMEM>>>(aggbuf, lin2_w, lin2_b, tmpbuf, N);
    // 6. out = tmp @ lin^T + b
    node_gemm<false, true><<<(N + TE - 1) / TE, 256, NODE_SMEM>>>(tmpbuf, lin_w, lin_b, (float*)d_out, N);
}